// round 5
// baseline (speedup 1.0000x reference)
#include <cuda_runtime.h>

#define NN 10000
#define NE 160000
#define INV3 0.5773502691896258f
#define SKN  0.03952847075210474f      /* 1/sqrt(640) */
#define LN   0.0027621358640099513f    /* 1/sqrt(128)/32 */

typedef unsigned long long u64;

__device__ float4 g_xu[NN * 64];        // packed (x0, x1x, x1y, x1z)
__device__ float g_scs[NN * 128];
__device__ float g_scv[NN * 192];
__device__ float g_tw[(size_t)NE * 256];
__device__ int g_cnt[NN], g_row[NN + 1], g_cur[NN], g_csr[NE], g_snd[NE];

__device__ __forceinline__ float silu_f(float x) { return x / (1.0f + __expf(-x)); }

__device__ __forceinline__ u64 dup2(float x) {
    u64 r; asm("mov.b64 %0, {%1, %1};" : "=l"(r) : "f"(x)); return r;
}
__device__ __forceinline__ void fma2(u64& d, u64 a, u64 b) {
    asm("fma.rn.f32x2 %0, %1, %2, %0;" : "+l"(d) : "l"(a), "l"(b));
}
__device__ __forceinline__ float2 unp2(u64 v) {
    float2 f; asm("mov.b64 {%0, %1}, %2;" : "=f"(f.x), "=f"(f.y) : "l"(v)); return f;
}

// ================= K1: up-projection + skip connections =================
__global__ void __launch_bounds__(256) node_prep(
    const float* __restrict__ attrs, const float* __restrict__ feats,
    const float* __restrict__ Wup0, const float* __restrict__ Wup1,
    const float* __restrict__ Wsks, const float* __restrict__ Wskv)
{
    __shared__ float sx0[32 * 65];
    __shared__ float sx1[32 * 193];
    __shared__ float sat[32 * 11];
    const int t = threadIdx.x;
    const int n0 = blockIdx.x * 32;

    for (int idx = t; idx < 32 * 256; idx += 256) {
        int m = idx >> 8, c = idx & 255;
        int n = n0 + m;
        float v = (n < NN) ? feats[(size_t)n * 256 + c] : 0.f;
        if (c < 64) sx0[m * 65 + c] = v; else sx1[m * 193 + (c - 64)] = v;
    }
    for (int idx = t; idx < 32 * 10; idx += 256) {
        int m = idx / 10, a = idx - m * 10;
        int n = n0 + m;
        sat[m * 11 + a] = (n < NN) ? attrs[n * 10 + a] : 0.f;
    }
    __syncthreads();

    // ---- up projections -> packed float4 (scalar; small) ----
    {
        const int v = t & 63, mg = t >> 6;
        float a0[8], a1[8][3];
        #pragma unroll
        for (int j = 0; j < 8; j++) { a0[j] = 0.f; a1[j][0] = a1[j][1] = a1[j][2] = 0.f; }
        for (int u = 0; u < 64; u++) {
            float w0 = Wup0[u * 64 + v];
            float w1 = Wup1[u * 64 + v];
            #pragma unroll
            for (int j = 0; j < 8; j++) {
                int m = mg * 8 + j;
                a0[j] += sx0[m * 65 + u] * w0;
                const float* xv = &sx1[m * 193 + u * 3];
                a1[j][0] += xv[0] * w1;
                a1[j][1] += xv[1] * w1;
                a1[j][2] += xv[2] * w1;
            }
        }
        #pragma unroll
        for (int j = 0; j < 8; j++) {
            int n = n0 + mg * 8 + j;
            if (n < NN)
                g_xu[n * 64 + v] = make_float4(a0[j] * 0.125f, a1[j][0] * 0.125f,
                                               a1[j][1] * 0.125f, a1[j][2] * 0.125f);
        }
    }

    // ---- sc_s (FFMA2 over channel pairs) ----
    {
        const int gv = t & 31, gm = t >> 5;
        u64 acc[4][2];
        #pragma unroll
        for (int j = 0; j < 4; j++) { acc[j][0] = 0ull; acc[j][1] = 0ull; }
        for (int u = 0; u < 64; u++) {
            float xj[4];
            #pragma unroll
            for (int j = 0; j < 4; j++) xj[j] = sx0[(gm * 4 + j) * 65 + u];
            #pragma unroll
            for (int a = 0; a < 10; a++) {
                ulonglong2 b = *reinterpret_cast<const ulonglong2*>(&Wsks[(u * 10 + a) * 128 + gv * 4]);
                #pragma unroll
                for (int j = 0; j < 4; j++) {
                    u64 pd = dup2(xj[j] * sat[(gm * 4 + j) * 11 + a]);
                    fma2(acc[j][0], pd, b.x);
                    fma2(acc[j][1], pd, b.y);
                }
            }
        }
        #pragma unroll
        for (int j = 0; j < 4; j++) {
            int n = n0 + gm * 4 + j;
            if (n < NN) {
                float2 f0 = unp2(acc[j][0]);
                float2 f1 = unp2(acc[j][1]);
                g_scs[n * 128 + gv * 4 + 0] = f0.x * SKN;
                g_scs[n * 128 + gv * 4 + 1] = f0.y * SKN;
                g_scs[n * 128 + gv * 4 + 2] = f1.x * SKN;
                g_scs[n * 128 + gv * 4 + 3] = f1.y * SKN;
            }
        }
    }

    // ---- sc_v (FFMA2: the (2v) channel pair is one u64 accumulator) ----
    {
        const int gv = t & 31, gm = t >> 5;
        u64 acc[4][3];
        #pragma unroll
        for (int j = 0; j < 4; j++)
            #pragma unroll
            for (int i = 0; i < 3; i++) acc[j][i] = 0ull;
        for (int u = 0; u < 64; u++) {
            float xv[4][3];
            #pragma unroll
            for (int j = 0; j < 4; j++) {
                const float* p = &sx1[(gm * 4 + j) * 193 + u * 3];
                xv[j][0] = p[0]; xv[j][1] = p[1]; xv[j][2] = p[2];
            }
            #pragma unroll
            for (int a = 0; a < 10; a++) {
                u64 b2 = *reinterpret_cast<const u64*>(&Wskv[(u * 10 + a) * 64 + gv * 2]);
                #pragma unroll
                for (int j = 0; j < 4; j++) {
                    float pa = sat[(gm * 4 + j) * 11 + a];
                    #pragma unroll
                    for (int i = 0; i < 3; i++) {
                        u64 pd = dup2(xv[j][i] * pa);
                        fma2(acc[j][i], pd, b2);
                    }
                }
            }
        }
        #pragma unroll
        for (int j = 0; j < 4; j++) {
            int n = n0 + gm * 4 + j;
            if (n < NN) {
                #pragma unroll
                for (int i = 0; i < 3; i++) {
                    float2 f = unp2(acc[j][i]);
                    g_scv[n * 192 + (gv * 2 + 0) * 3 + i] = f.x * SKN;
                    g_scv[n * 192 + (gv * 2 + 1) * 3 + i] = f.y * SKN;
                }
            }
        }
    }
}

// ================= CSR build =================
__global__ void zero_k() {
    int i = blockIdx.x * blockDim.x + threadIdx.x;
    if (i < NN) g_cnt[i] = 0;
}
__global__ void hist_k(const int* __restrict__ ei) {
    int e = blockIdx.x * blockDim.x + threadIdx.x;
    if (e < NE) atomicAdd(&g_cnt[ei[NE + e]], 1);
}
__global__ void __launch_bounds__(1024) scan_k() {
    __shared__ int wsum[32];
    const int t = threadIdx.x;
    const int lane = t & 31, w = t >> 5;
    int base = t * 10, loc[10], s = 0;
    #pragma unroll
    for (int i = 0; i < 10; i++) {
        int idx = base + i;
        loc[i] = (idx < NN) ? g_cnt[idx] : 0;
        s += loc[i];
    }
    int v = s;
    #pragma unroll
    for (int off = 1; off < 32; off <<= 1) {
        int n = __shfl_up_sync(0xFFFFFFFFu, v, off);
        if (lane >= off) v += n;
    }
    if (lane == 31) wsum[w] = v;
    __syncthreads();
    if (w == 0) {
        int x = wsum[lane];
        #pragma unroll
        for (int off = 1; off < 32; off <<= 1) {
            int n = __shfl_up_sync(0xFFFFFFFFu, x, off);
            if (lane >= off) x += n;
        }
        wsum[lane] = x;
    }
    __syncthreads();
    int run = v - s + ((w > 0) ? wsum[w - 1] : 0);
    #pragma unroll
    for (int i = 0; i < 10; i++) {
        int idx = base + i;
        if (idx < NN) { g_row[idx] = run; g_cur[idx] = run; run += loc[i]; }
    }
    if (t == 1023) g_row[NN] = run;
}
__global__ void fill_k(const int* __restrict__ ei) {
    int e = blockIdx.x * blockDim.x + threadIdx.x;
    if (e < NE) {
        int pos = atomicAdd(&g_cur[ei[NE + e]], 1);
        g_csr[pos] = e;
    }
}
__global__ void sort_k(const int* __restrict__ ei) {
    int n = blockIdx.x * blockDim.x + threadIdx.x;
    if (n < NN) {
        int b = g_row[n], e = g_row[n + 1];
        for (int i = b + 1; i < e; i++) {
            int v = g_csr[i], j = i - 1;
            while (j >= b && g_csr[j] > v) { g_csr[j + 1] = g_csr[j]; j--; }
            g_csr[j + 1] = v;
        }
        for (int i = b; i < e; i++) g_snd[i] = ei[g_csr[i]];
    }
}

// ================= K2: fused edge MLP (FFMA2, minimal-diff structure) =================
__device__ __forceinline__ void layer64(const float* __restrict__ hin,
                                        const float* __restrict__ W,
                                        float* __restrict__ hout, int t)
{
    const int gv = t & 15, ge = t >> 4;
    u64 acc[4][2];
    #pragma unroll
    for (int j = 0; j < 4; j++) { acc[j][0] = 0ull; acc[j][1] = 0ull; }
    #pragma unroll 4
    for (int k0 = 0; k0 < 64; k0 += 4) {
        float4 aj[4];
        #pragma unroll
        for (int j = 0; j < 4; j++)
            aj[j] = *reinterpret_cast<const float4*>(&hin[(ge * 4 + j) * 68 + k0]);
        #pragma unroll
        for (int kk = 0; kk < 4; kk++) {
            ulonglong2 b = *reinterpret_cast<const ulonglong2*>(&W[(k0 + kk) * 64 + gv * 4]);
            #pragma unroll
            for (int j = 0; j < 4; j++) {
                float a = (kk == 0) ? aj[j].x : (kk == 1) ? aj[j].y : (kk == 2) ? aj[j].z : aj[j].w;
                u64 ad = dup2(a);
                fma2(acc[j][0], ad, b.x);
                fma2(acc[j][1], ad, b.y);
            }
        }
    }
    #pragma unroll
    for (int j = 0; j < 4; j++) {
        float2 f0 = unp2(acc[j][0]);
        float2 f1 = unp2(acc[j][1]);
        float* o = &hout[(ge * 4 + j) * 68 + gv * 4];
        o[0] = silu_f(f0.x * 0.125f);
        o[1] = silu_f(f0.y * 0.125f);
        o[2] = silu_f(f1.x * 0.125f);
        o[3] = silu_f(f1.y * 0.125f);
    }
}

__global__ void __launch_bounds__(256) edge_mlp(
    const float* __restrict__ ef, const float* __restrict__ M1,
    const float* __restrict__ M2, const float* __restrict__ M3,
    const float* __restrict__ M4)
{
    __shared__ float ef_s[64 * 9];
    __shared__ float ha[64 * 68];
    __shared__ float hb[64 * 68];
    const int t = threadIdx.x;
    const int e0 = blockIdx.x * 64;

    for (int idx = t; idx < 64 * 8; idx += 256) {
        int m = idx >> 3, k = idx & 7;
        ef_s[m * 9 + k] = ef[(size_t)(e0 + m) * 8 + k];
    }
    __syncthreads();

    // layer 1 (k=8)
    {
        const int gv = t & 15, ge = t >> 4;
        u64 acc[4][2];
        #pragma unroll
        for (int j = 0; j < 4; j++) { acc[j][0] = 0ull; acc[j][1] = 0ull; }
        #pragma unroll
        for (int k = 0; k < 8; k++) {
            ulonglong2 b = *reinterpret_cast<const ulonglong2*>(&M1[k * 64 + gv * 4]);
            #pragma unroll
            for (int j = 0; j < 4; j++) {
                u64 ad = dup2(ef_s[(ge * 4 + j) * 9 + k]);
                fma2(acc[j][0], ad, b.x);
                fma2(acc[j][1], ad, b.y);
            }
        }
        #pragma unroll
        for (int j = 0; j < 4; j++) {
            float2 f0 = unp2(acc[j][0]);
            float2 f1 = unp2(acc[j][1]);
            float* o = &ha[(ge * 4 + j) * 68 + gv * 4];
            o[0] = silu_f(f0.x * 0.35355339059327373f);
            o[1] = silu_f(f0.y * 0.35355339059327373f);
            o[2] = silu_f(f1.x * 0.35355339059327373f);
            o[3] = silu_f(f1.y * 0.35355339059327373f);
        }
    }
    __syncthreads();
    layer64(ha, M2, hb, t);
    __syncthreads();
    layer64(hb, M3, ha, t);
    __syncthreads();

    // output layer (256 wide, no silu)
    {
        const int ce = t & 63, eg = t >> 6;
        #pragma unroll
        for (int rep = 0; rep < 4; rep++) {
            int eb = (rep * 4 + eg) * 4;
            u64 acc[4][2];
            #pragma unroll
            for (int j = 0; j < 4; j++) { acc[j][0] = 0ull; acc[j][1] = 0ull; }
            #pragma unroll 4
            for (int k0 = 0; k0 < 64; k0 += 4) {
                float4 aj[4];
                #pragma unroll
                for (int j = 0; j < 4; j++)
                    aj[j] = *reinterpret_cast<const float4*>(&ha[(eb + j) * 68 + k0]);
                #pragma unroll
                for (int kk = 0; kk < 4; kk++) {
                    ulonglong2 b = *reinterpret_cast<const ulonglong2*>(&M4[(k0 + kk) * 256 + ce * 4]);
                    #pragma unroll
                    for (int j = 0; j < 4; j++) {
                        float a = (kk == 0) ? aj[j].x : (kk == 1) ? aj[j].y : (kk == 2) ? aj[j].z : aj[j].w;
                        u64 ad = dup2(a);
                        fma2(acc[j][0], ad, b.x);
                        fma2(acc[j][1], ad, b.y);
                    }
                }
            }
            #pragma unroll
            for (int j = 0; j < 4; j++) {
                float2 f0 = unp2(acc[j][0]);
                float2 f1 = unp2(acc[j][1]);
                float4 o = make_float4(f0.x * 0.125f, f0.y * 0.125f,
                                       f1.x * 0.125f, f1.y * 0.125f);
                *reinterpret_cast<float4*>(&g_tw[(size_t)(e0 + eb + j) * 256 + ce * 4]) = o;
            }
        }
    }
}

// ================= K4: gather + linear + gate + output =================
__global__ void __launch_bounds__(256) gather_final(
    const float* __restrict__ ear, const float* __restrict__ eai,
    const float* __restrict__ Wls, const float* __restrict__ Wlv,
    float* __restrict__ out)
{
    __shared__ float2 s_ms[4][128];
    __shared__ float2 s_mv[4][128][3];
    const int t = threadIdx.x;
    const int g = t >> 6, v = t & 63;
    const int n = blockIdx.x * 4 + g;

    float msr0 = 0.f, msr1 = 0.f, msi0 = 0.f, msi1 = 0.f;
    float mvr0[3] = {0.f, 0.f, 0.f}, mvr1[3] = {0.f, 0.f, 0.f};
    float mvi0[3] = {0.f, 0.f, 0.f}, mvi1[3] = {0.f, 0.f, 0.f};

    if (n < NN) {
        int b = g_row[n], ed = g_row[n + 1];
        for (int idx = b; idx < ed; idx++) {
            int e = g_csr[idx];
            int s = g_snd[idx];
            float4 yr = *reinterpret_cast<const float4*>(&ear[e * 4]);
            float4 yi = *reinterpret_cast<const float4*>(&eai[e * 4]);
            float4 x = g_xu[s * 64 + v];
            const float* twp = &g_tw[(size_t)e * 256];
            float wA = twp[v], wB = twp[64 + v], wC = twp[128 + v], wD = twp[192 + v];

            float dr = x.y * yr.y + x.z * yr.z + x.w * yr.w;
            float di = x.y * yi.y + x.z * yi.z + x.w * yi.w;
            msr0 += x.x * yr.x * wA;
            msi0 += x.x * yi.x * wA;
            msr1 += dr * INV3 * wD;
            msi1 += di * INV3 * wD;
            float xb = x.x * wB;
            mvr0[0] += xb * yr.y; mvr0[1] += xb * yr.z; mvr0[2] += xb * yr.w;
            mvi0[0] += xb * yi.y; mvi0[1] += xb * yi.z; mvi0[2] += xb * yi.w;
            float tcr = yr.x * wC, tci = yi.x * wC;
            mvr1[0] += x.y * tcr; mvr1[1] += x.z * tcr; mvr1[2] += x.w * tcr;
            mvi1[0] += x.y * tci; mvi1[1] += x.z * tci; mvi1[2] += x.w * tci;
        }
    }
    s_ms[g][v] = make_float2(msr0, msi0);
    s_ms[g][64 + v] = make_float2(msr1, msi1);
    #pragma unroll
    for (int i = 0; i < 3; i++) {
        s_mv[g][v][i] = make_float2(mvr0[i], mvi0[i]);
        s_mv[g][64 + v][i] = make_float2(mvr1[i], mvi1[i]);
    }
    __syncthreads();

    float lsr0 = 0.f, lsr1 = 0.f, lsi0 = 0.f, lsi1 = 0.f;
    float lvr[3] = {0.f, 0.f, 0.f}, lvi[3] = {0.f, 0.f, 0.f};
    #pragma unroll 4
    for (int u = 0; u < 128; u++) {
        float wa = Wls[u * 128 + v];
        float wb = Wls[u * 128 + 64 + v];
        float wv = Wlv[u * 64 + v];
        float2 m = s_ms[g][u];
        lsr0 += m.x * wa; lsr1 += m.x * wb;
        lsi0 += m.y * wa; lsi1 += m.y * wb;
        #pragma unroll
        for (int i = 0; i < 3; i++) {
            float2 mv = s_mv[g][u][i];
            lvr[i] += mv.x * wv;
            lvi[i] += mv.y * wv;
        }
    }

    if (n < NN) {
        float sr0 = lsr0 * LN + g_scs[n * 128 + v];
        float sr1 = lsr1 * LN + g_scs[n * 128 + 64 + v];
        float scal_r = silu_f(sr0);
        float gr = silu_f(sr1);
        float scal_i = silu_f(lsi0 * LN);
        float gi = silu_f(lsi1 * LN);
        float* o = out + (size_t)n * 512;
        o[v * 2 + 0] = scal_r;
        o[v * 2 + 1] = scal_i;
        #pragma unroll
        for (int i = 0; i < 3; i++) {
            float vr = (lvr[i] * LN + g_scv[n * 192 + v * 3 + i]) * gr;
            float vi = (lvi[i] * LN) * gi;
            int k = 64 + v * 3 + i;
            o[k * 2 + 0] = vr;
            o[k * 2 + 1] = vi;
        }
    }
}

// ================= launch =================
extern "C" void kernel_launch(void* const* d_in, const int* in_sizes, int n_in,
                              void* d_out, int out_size)
{
    const float* node_attrs = (const float*)d_in[0];
    const float* node_feats = (const float*)d_in[1];
    const float* ear        = (const float*)d_in[2];
    const float* eai        = (const float*)d_in[3];
    const float* ef         = (const float*)d_in[4];
    const float* Wup0       = (const float*)d_in[5];
    const float* Wup1       = (const float*)d_in[6];
    const float* M1         = (const float*)d_in[7];
    const float* M2         = (const float*)d_in[8];
    const float* M3         = (const float*)d_in[9];
    const float* M4         = (const float*)d_in[10];
    const float* Wls        = (const float*)d_in[11];
    const float* Wlv        = (const float*)d_in[12];
    const float* Wsks       = (const float*)d_in[13];
    const float* Wskv       = (const float*)d_in[14];
    const int*   ei         = (const int*)d_in[15];
    float* out = (float*)d_out;

    // edge_mlp kept at launch index 3 (the slot ncu captures)
    node_prep<<<(NN + 31) / 32, 256>>>(node_attrs, node_feats, Wup0, Wup1, Wsks, Wskv);
    zero_k<<<(NN + 255) / 256, 256>>>();
    hist_k<<<(NE + 255) / 256, 256>>>(ei);
    edge_mlp<<<NE / 64, 256>>>(ef, M1, M2, M3, M4);
    scan_k<<<1, 1024>>>();
    fill_k<<<(NE + 255) / 256, 256>>>(ei);
    sort_k<<<(NN + 127) / 128, 128>>>(ei);
    gather_final<<<(NN + 3) / 4, 256>>>(ear, eai, Wls, Wlv, out);
}

// round 6
// speedup vs baseline: 1.1274x; 1.1274x over previous
#include <cuda_runtime.h>

#define NN 10000
#define NE 160000
#define INV3 0.5773502691896258f
#define SKN  0.03952847075210474f      /* 1/sqrt(640) */
#define LN   0.0027621358640099513f    /* 1/sqrt(128)/32 */

__device__ float4 g_xu[NN * 64];        // packed (x0, x1x, x1y, x1z)
__device__ float g_scs[NN * 128];
__device__ float g_scv[NN * 192];
__device__ float g_tw[(size_t)NE * 256];
__device__ int g_cnt[NN], g_row[NN + 1], g_cur[NN], g_csr[NE], g_snd[NE];

__device__ __forceinline__ float silu_f(float x) { return x / (1.0f + __expf(-x)); }

// ================= K1: up-projection + skip connections (scalar, R3) ==========
__global__ void __launch_bounds__(256) node_prep(
    const float* __restrict__ attrs, const float* __restrict__ feats,
    const float* __restrict__ Wup0, const float* __restrict__ Wup1,
    const float* __restrict__ Wsks, const float* __restrict__ Wskv)
{
    __shared__ float sx0[32 * 65];
    __shared__ float sx1[32 * 193];
    __shared__ float sat[32 * 11];
    const int t = threadIdx.x;
    const int n0 = blockIdx.x * 32;

    for (int idx = t; idx < 32 * 256; idx += 256) {
        int m = idx >> 8, c = idx & 255;
        int n = n0 + m;
        float v = (n < NN) ? feats[(size_t)n * 256 + c] : 0.f;
        if (c < 64) sx0[m * 65 + c] = v; else sx1[m * 193 + (c - 64)] = v;
    }
    for (int idx = t; idx < 32 * 10; idx += 256) {
        int m = idx / 10, a = idx - m * 10;
        int n = n0 + m;
        sat[m * 11 + a] = (n < NN) ? attrs[n * 10 + a] : 0.f;
    }
    __syncthreads();

    // ---- up projections -> packed float4 ----
    {
        const int v = t & 63, mg = t >> 6;
        float a0[8], a1[8][3];
        #pragma unroll
        for (int j = 0; j < 8; j++) { a0[j] = 0.f; a1[j][0] = a1[j][1] = a1[j][2] = 0.f; }
        for (int u = 0; u < 64; u++) {
            float w0 = Wup0[u * 64 + v];
            float w1 = Wup1[u * 64 + v];
            #pragma unroll
            for (int j = 0; j < 8; j++) {
                int m = mg * 8 + j;
                a0[j] += sx0[m * 65 + u] * w0;
                const float* xv = &sx1[m * 193 + u * 3];
                a1[j][0] += xv[0] * w1;
                a1[j][1] += xv[1] * w1;
                a1[j][2] += xv[2] * w1;
            }
        }
        #pragma unroll
        for (int j = 0; j < 8; j++) {
            int n = n0 + mg * 8 + j;
            if (n < NN)
                g_xu[n * 64 + v] = make_float4(a0[j] * 0.125f, a1[j][0] * 0.125f,
                                               a1[j][1] * 0.125f, a1[j][2] * 0.125f);
        }
    }

    // ---- sc_s ----
    {
        const int gv = t & 31, gm = t >> 5;
        float acc[4][4];
        #pragma unroll
        for (int j = 0; j < 4; j++) { acc[j][0] = acc[j][1] = acc[j][2] = acc[j][3] = 0.f; }
        for (int u = 0; u < 64; u++) {
            float xj[4];
            #pragma unroll
            for (int j = 0; j < 4; j++) xj[j] = sx0[(gm * 4 + j) * 65 + u];
            #pragma unroll
            for (int a = 0; a < 10; a++) {
                float4 b = *reinterpret_cast<const float4*>(&Wsks[(u * 10 + a) * 128 + gv * 4]);
                #pragma unroll
                for (int j = 0; j < 4; j++) {
                    float p = xj[j] * sat[(gm * 4 + j) * 11 + a];
                    acc[j][0] += p * b.x; acc[j][1] += p * b.y;
                    acc[j][2] += p * b.z; acc[j][3] += p * b.w;
                }
            }
        }
        #pragma unroll
        for (int j = 0; j < 4; j++) {
            int n = n0 + gm * 4 + j;
            if (n < NN) {
                #pragma unroll
                for (int l = 0; l < 4; l++) g_scs[n * 128 + gv * 4 + l] = acc[j][l] * SKN;
            }
        }
    }

    // ---- sc_v ----
    {
        const int gv = t & 31, gm = t >> 5;
        float acc[4][3][2];
        #pragma unroll
        for (int j = 0; j < 4; j++)
            #pragma unroll
            for (int i = 0; i < 3; i++) { acc[j][i][0] = 0.f; acc[j][i][1] = 0.f; }
        for (int u = 0; u < 64; u++) {
            float xv[4][3];
            #pragma unroll
            for (int j = 0; j < 4; j++) {
                const float* p = &sx1[(gm * 4 + j) * 193 + u * 3];
                xv[j][0] = p[0]; xv[j][1] = p[1]; xv[j][2] = p[2];
            }
            #pragma unroll
            for (int a = 0; a < 10; a++) {
                float2 b = *reinterpret_cast<const float2*>(&Wskv[(u * 10 + a) * 64 + gv * 2]);
                #pragma unroll
                for (int j = 0; j < 4; j++) {
                    float pa = sat[(gm * 4 + j) * 11 + a];
                    #pragma unroll
                    for (int i = 0; i < 3; i++) {
                        float p = xv[j][i] * pa;
                        acc[j][i][0] += p * b.x;
                        acc[j][i][1] += p * b.y;
                    }
                }
            }
        }
        #pragma unroll
        for (int j = 0; j < 4; j++) {
            int n = n0 + gm * 4 + j;
            if (n < NN) {
                #pragma unroll
                for (int i = 0; i < 3; i++) {
                    g_scv[n * 192 + (gv * 2 + 0) * 3 + i] = acc[j][i][0] * SKN;
                    g_scv[n * 192 + (gv * 2 + 1) * 3 + i] = acc[j][i][1] * SKN;
                }
            }
        }
    }
}

// ================= CSR build =================
__global__ void hist_k(const int* __restrict__ ei) {
    int e = blockIdx.x * blockDim.x + threadIdx.x;
    if (e < NE) atomicAdd(&g_cnt[ei[NE + e]], 1);
}
// scan also re-zeroes g_cnt for the next graph replay (self-restoring state)
__global__ void __launch_bounds__(1024) scan_k() {
    __shared__ int wsum[32];
    const int t = threadIdx.x;
    const int lane = t & 31, w = t >> 5;
    int base = t * 10, loc[10], s = 0;
    #pragma unroll
    for (int i = 0; i < 10; i++) {
        int idx = base + i;
        loc[i] = (idx < NN) ? g_cnt[idx] : 0;
        if (idx < NN) g_cnt[idx] = 0;
        s += loc[i];
    }
    int v = s;
    #pragma unroll
    for (int off = 1; off < 32; off <<= 1) {
        int n = __shfl_up_sync(0xFFFFFFFFu, v, off);
        if (lane >= off) v += n;
    }
    if (lane == 31) wsum[w] = v;
    __syncthreads();
    if (w == 0) {
        int x = wsum[lane];
        #pragma unroll
        for (int off = 1; off < 32; off <<= 1) {
            int n = __shfl_up_sync(0xFFFFFFFFu, x, off);
            if (lane >= off) x += n;
        }
        wsum[lane] = x;
    }
    __syncthreads();
    int run = v - s + ((w > 0) ? wsum[w - 1] : 0);
    #pragma unroll
    for (int i = 0; i < 10; i++) {
        int idx = base + i;
        if (idx < NN) { g_row[idx] = run; g_cur[idx] = run; run += loc[i]; }
    }
    if (t == 1023) g_row[NN] = run;
}
__global__ void fill_k(const int* __restrict__ ei) {
    int e = blockIdx.x * blockDim.x + threadIdx.x;
    if (e < NE) {
        int pos = atomicAdd(&g_cur[ei[NE + e]], 1);
        g_csr[pos] = e;
    }
}
__global__ void sort_k(const int* __restrict__ ei) {
    int n = blockIdx.x * blockDim.x + threadIdx.x;
    if (n < NN) {
        int b = g_row[n], e = g_row[n + 1];
        for (int i = b + 1; i < e; i++) {
            int v = g_csr[i], j = i - 1;
            while (j >= b && g_csr[j] > v) { g_csr[j + 1] = g_csr[j]; j--; }
            g_csr[j + 1] = v;
        }
        for (int i = b; i < e; i++) g_snd[i] = ei[g_csr[i]];
    }
}

// ================= K2: fused edge MLP (scalar FFMA, R3 winner) =================
__device__ __forceinline__ void layer64(const float* __restrict__ hin,
                                        const float* __restrict__ W,
                                        float* __restrict__ hout, int t)
{
    const int gv = t & 15, ge = t >> 4;
    float acc[4][4];
    #pragma unroll
    for (int j = 0; j < 4; j++) { acc[j][0] = acc[j][1] = acc[j][2] = acc[j][3] = 0.f; }
    #pragma unroll 4
    for (int k0 = 0; k0 < 64; k0 += 4) {
        float4 aj[4];
        #pragma unroll
        for (int j = 0; j < 4; j++)
            aj[j] = *reinterpret_cast<const float4*>(&hin[(ge * 4 + j) * 68 + k0]);
        #pragma unroll
        for (int kk = 0; kk < 4; kk++) {
            float4 b = *reinterpret_cast<const float4*>(&W[(k0 + kk) * 64 + gv * 4]);
            #pragma unroll
            for (int j = 0; j < 4; j++) {
                float a = (kk == 0) ? aj[j].x : (kk == 1) ? aj[j].y : (kk == 2) ? aj[j].z : aj[j].w;
                acc[j][0] += a * b.x; acc[j][1] += a * b.y;
                acc[j][2] += a * b.z; acc[j][3] += a * b.w;
            }
        }
    }
    #pragma unroll
    for (int j = 0; j < 4; j++)
        #pragma unroll
        for (int l = 0; l < 4; l++)
            hout[(ge * 4 + j) * 68 + gv * 4 + l] = silu_f(acc[j][l] * 0.125f);
}

__global__ void __launch_bounds__(256) edge_mlp(
    const float* __restrict__ ef, const float* __restrict__ M1,
    const float* __restrict__ M2, const float* __restrict__ M3,
    const float* __restrict__ M4)
{
    __shared__ float ef_s[64 * 9];
    __shared__ float ha[64 * 68];
    __shared__ float hb[64 * 68];
    const int t = threadIdx.x;
    const int e0 = blockIdx.x * 64;

    for (int idx = t; idx < 64 * 8; idx += 256) {
        int m = idx >> 3, k = idx & 7;
        ef_s[m * 9 + k] = ef[(size_t)(e0 + m) * 8 + k];
    }
    __syncthreads();

    // layer 1 (k=8)
    {
        const int gv = t & 15, ge = t >> 4;
        float acc[4][4];
        #pragma unroll
        for (int j = 0; j < 4; j++) { acc[j][0] = acc[j][1] = acc[j][2] = acc[j][3] = 0.f; }
        #pragma unroll
        for (int k = 0; k < 8; k++) {
            float4 b = *reinterpret_cast<const float4*>(&M1[k * 64 + gv * 4]);
            #pragma unroll
            for (int j = 0; j < 4; j++) {
                float a = ef_s[(ge * 4 + j) * 9 + k];
                acc[j][0] += a * b.x; acc[j][1] += a * b.y;
                acc[j][2] += a * b.z; acc[j][3] += a * b.w;
            }
        }
        #pragma unroll
        for (int j = 0; j < 4; j++)
            #pragma unroll
            for (int l = 0; l < 4; l++)
                ha[(ge * 4 + j) * 68 + gv * 4 + l] = silu_f(acc[j][l] * 0.35355339059327373f);
    }
    __syncthreads();
    layer64(ha, M2, hb, t);
    __syncthreads();
    layer64(hb, M3, ha, t);
    __syncthreads();

    // output layer (256 wide, no silu)
    {
        const int ce = t & 63, eg = t >> 6;
        #pragma unroll
        for (int rep = 0; rep < 4; rep++) {
            int eb = (rep * 4 + eg) * 4;
            float acc[4][4];
            #pragma unroll
            for (int j = 0; j < 4; j++) { acc[j][0] = acc[j][1] = acc[j][2] = acc[j][3] = 0.f; }
            #pragma unroll 4
            for (int k0 = 0; k0 < 64; k0 += 4) {
                float4 aj[4];
                #pragma unroll
                for (int j = 0; j < 4; j++)
                    aj[j] = *reinterpret_cast<const float4*>(&ha[(eb + j) * 68 + k0]);
                #pragma unroll
                for (int kk = 0; kk < 4; kk++) {
                    float4 b = *reinterpret_cast<const float4*>(&M4[(k0 + kk) * 256 + ce * 4]);
                    #pragma unroll
                    for (int j = 0; j < 4; j++) {
                        float a = (kk == 0) ? aj[j].x : (kk == 1) ? aj[j].y : (kk == 2) ? aj[j].z : aj[j].w;
                        acc[j][0] += a * b.x; acc[j][1] += a * b.y;
                        acc[j][2] += a * b.z; acc[j][3] += a * b.w;
                    }
                }
            }
            #pragma unroll
            for (int j = 0; j < 4; j++) {
                float4 o = make_float4(acc[j][0] * 0.125f, acc[j][1] * 0.125f,
                                       acc[j][2] * 0.125f, acc[j][3] * 0.125f);
                *reinterpret_cast<float4*>(&g_tw[(size_t)(e0 + eb + j) * 256 + ce * 4]) = o;
            }
        }
    }
}

// ================= K4: gather (2-way edge split) + linear + gate + output ======
// 256 threads = 2 nodes; per node: 2 halves (r) x 64 channels (v).
__global__ void __launch_bounds__(256) gather_final(
    const float* __restrict__ ear, const float* __restrict__ eai,
    const float* __restrict__ Wls, const float* __restrict__ Wlv,
    float* __restrict__ out)
{
    __shared__ float2 sms[2][2][128];
    __shared__ float2 smv[2][2][128][3];
    __shared__ float sfin[2][64][10];
    const int t = threadIdx.x;
    const int g = t >> 7, r = (t >> 6) & 1, v = t & 63;
    const int n = blockIdx.x * 2 + g;

    float msr0 = 0.f, msr1 = 0.f, msi0 = 0.f, msi1 = 0.f;
    float mvr0[3] = {0.f, 0.f, 0.f}, mvr1[3] = {0.f, 0.f, 0.f};
    float mvi0[3] = {0.f, 0.f, 0.f}, mvi1[3] = {0.f, 0.f, 0.f};

    if (n < NN) {
        int b = g_row[n], ed = g_row[n + 1];
        for (int idx = b + r; idx < ed; idx += 2) {
            int e = g_csr[idx];
            int s = g_snd[idx];
            float4 yr = *reinterpret_cast<const float4*>(&ear[e * 4]);
            float4 yi = *reinterpret_cast<const float4*>(&eai[e * 4]);
            float4 x = g_xu[s * 64 + v];
            const float* twp = &g_tw[(size_t)e * 256];
            float wA = twp[v], wB = twp[64 + v], wC = twp[128 + v], wD = twp[192 + v];

            float dr = x.y * yr.y + x.z * yr.z + x.w * yr.w;
            float di = x.y * yi.y + x.z * yi.z + x.w * yi.w;
            msr0 += x.x * yr.x * wA;
            msi0 += x.x * yi.x * wA;
            msr1 += dr * INV3 * wD;
            msi1 += di * INV3 * wD;
            float xb = x.x * wB;
            mvr0[0] += xb * yr.y; mvr0[1] += xb * yr.z; mvr0[2] += xb * yr.w;
            mvi0[0] += xb * yi.y; mvi0[1] += xb * yi.z; mvi0[2] += xb * yi.w;
            float tcr = yr.x * wC, tci = yi.x * wC;
            mvr1[0] += x.y * tcr; mvr1[1] += x.z * tcr; mvr1[2] += x.w * tcr;
            mvi1[0] += x.y * tci; mvi1[1] += x.z * tci; mvi1[2] += x.w * tci;
        }
    }
    sms[g][r][v] = make_float2(msr0, msi0);
    sms[g][r][64 + v] = make_float2(msr1, msi1);
    #pragma unroll
    for (int i = 0; i < 3; i++) {
        smv[g][r][v][i] = make_float2(mvr0[i], mvi0[i]);
        smv[g][r][64 + v][i] = make_float2(mvr1[i], mvi1[i]);
    }
    __syncthreads();

    // combine halves into half 0 (each thread owns u = r*64+v)
    {
        int u = r * 64 + v;
        float2 a = sms[g][0][u], b = sms[g][1][u];
        sms[g][0][u] = make_float2(a.x + b.x, a.y + b.y);
        #pragma unroll
        for (int i = 0; i < 3; i++) {
            float2 c = smv[g][0][u][i], d = smv[g][1][u][i];
            smv[g][0][u][i] = make_float2(c.x + d.x, c.y + d.y);
        }
    }
    __syncthreads();

    // final linear: each half covers 64 u's
    float lsr0 = 0.f, lsr1 = 0.f, lsi0 = 0.f, lsi1 = 0.f;
    float lvr[3] = {0.f, 0.f, 0.f}, lvi[3] = {0.f, 0.f, 0.f};
    const int ub = r * 64;
    #pragma unroll 4
    for (int u2 = 0; u2 < 64; u2++) {
        int u = ub + u2;
        float wa = Wls[u * 128 + v];
        float wb = Wls[u * 128 + 64 + v];
        float wv = Wlv[u * 64 + v];
        float2 m = sms[g][0][u];
        lsr0 += m.x * wa; lsr1 += m.x * wb;
        lsi0 += m.y * wa; lsi1 += m.y * wb;
        #pragma unroll
        for (int i = 0; i < 3; i++) {
            float2 mv = smv[g][0][u][i];
            lvr[i] += mv.x * wv;
            lvi[i] += mv.y * wv;
        }
    }

    // half 1 publishes partials; half 0 combines + writes
    if (r == 1) {
        float* p = sfin[g][v];
        p[0] = lsr0; p[1] = lsr1; p[2] = lsi0; p[3] = lsi1;
        p[4] = lvr[0]; p[5] = lvr[1]; p[6] = lvr[2];
        p[7] = lvi[0]; p[8] = lvi[1]; p[9] = lvi[2];
    }
    __syncthreads();
    if (r == 0 && n < NN) {
        const float* p = sfin[g][v];
        lsr0 += p[0]; lsr1 += p[1]; lsi0 += p[2]; lsi1 += p[3];
        lvr[0] += p[4]; lvr[1] += p[5]; lvr[2] += p[6];
        lvi[0] += p[7]; lvi[1] += p[8]; lvi[2] += p[9];

        float sr0 = lsr0 * LN + g_scs[n * 128 + v];
        float sr1 = lsr1 * LN + g_scs[n * 128 + 64 + v];
        float scal_r = silu_f(sr0);
        float gr = silu_f(sr1);
        float scal_i = silu_f(lsi0 * LN);
        float gi = silu_f(lsi1 * LN);
        float* o = out + (size_t)n * 512;
        o[v * 2 + 0] = scal_r;
        o[v * 2 + 1] = scal_i;
        #pragma unroll
        for (int i = 0; i < 3; i++) {
            float vr = (lvr[i] * LN + g_scv[n * 192 + v * 3 + i]) * gr;
            float vi = (lvi[i] * LN) * gi;
            int k = 64 + v * 3 + i;
            o[k * 2 + 0] = vr;
            o[k * 2 + 1] = vi;
        }
    }
}

// ================= launch =================
extern "C" void kernel_launch(void* const* d_in, const int* in_sizes, int n_in,
                              void* d_out, int out_size)
{
    const float* node_attrs = (const float*)d_in[0];
    const float* node_feats = (const float*)d_in[1];
    const float* ear        = (const float*)d_in[2];
    const float* eai        = (const float*)d_in[3];
    const float* ef         = (const float*)d_in[4];
    const float* Wup0       = (const float*)d_in[5];
    const float* Wup1       = (const float*)d_in[6];
    const float* M1         = (const float*)d_in[7];
    const float* M2         = (const float*)d_in[8];
    const float* M3         = (const float*)d_in[9];
    const float* M4         = (const float*)d_in[10];
    const float* Wls        = (const float*)d_in[11];
    const float* Wlv        = (const float*)d_in[12];
    const float* Wsks       = (const float*)d_in[13];
    const float* Wskv       = (const float*)d_in[14];
    const int*   ei         = (const int*)d_in[15];
    float* out = (float*)d_out;

    // node_prep placed at launch index 3 (the slot ncu captures)
    hist_k<<<(NE + 255) / 256, 256>>>(ei);
    scan_k<<<1, 1024>>>();
    fill_k<<<(NE + 255) / 256, 256>>>(ei);
    node_prep<<<(NN + 31) / 32, 256>>>(node_attrs, node_feats, Wup0, Wup1, Wsks, Wskv);
    sort_k<<<(NN + 127) / 128, 128>>>(ei);
    edge_mlp<<<NE / 64, 256>>>(ef, M1, M2, M3, M4);
    gather_final<<<(NN + 1) / 2, 256>>>(ear, eai, Wls, Wlv, out);
}

// round 7
// speedup vs baseline: 1.1895x; 1.0550x over previous
#include <cuda_runtime.h>

#define NN 10000
#define NE 160000
#define INV3 0.5773502691896258f
#define SKN  0.03952847075210474f      /* 1/sqrt(640) */
#define LN   0.0027621358640099513f    /* 1/sqrt(128)/32 */

__device__ float4 g_xu[NN * 64];        // packed (x0, x1x, x1y, x1z)
__device__ float g_scs[NN * 128];
__device__ float g_scv[NN * 192];
__device__ float g_tw[(size_t)NE * 256];
__device__ int g_cnt[NN], g_row[NN + 1], g_cur[NN], g_csr[NE], g_snd[NE];

__device__ __forceinline__ float silu_f(float x) { return x / (1.0f + __expf(-x)); }

// ================= K1: up-projection + skip as smem-tiled GEMMs ==============
// dyn smem: sx0 2080 | sx1 6176 | sat 352 | Wt 10240 | Pt 8064  = 26912 floats
#define NP_SMEM_FLOATS 26912
__global__ void __launch_bounds__(256) node_prep(
    const float* __restrict__ attrs, const float* __restrict__ feats,
    const float* __restrict__ Wup0, const float* __restrict__ Wup1,
    const float* __restrict__ Wsks, const float* __restrict__ Wskv)
{
    extern __shared__ float sm[];
    float* sx0 = sm;                    // 32*65
    float* sx1 = sx0 + 2080;            // 32*193
    float* sat = sx1 + 6176;            // 32*11
    float* Wt  = sat + 352;             // up to 80*128
    float* Pt  = Wt + 10240;            // up to 96*84
    const int t = threadIdx.x;
    const int n0 = blockIdx.x * 32;

    for (int idx = t; idx < 32 * 256; idx += 256) {
        int m = idx >> 8, c = idx & 255;
        int n = n0 + m;
        float v = (n < NN) ? feats[(size_t)n * 256 + c] : 0.f;
        if (c < 64) sx0[m * 65 + c] = v; else sx1[m * 193 + (c - 64)] = v;
    }
    for (int idx = t; idx < 32 * 10; idx += 256) {
        int m = idx / 10, a = idx - m * 10;
        int n = n0 + m;
        sat[m * 11 + a] = (n < NN) ? attrs[n * 10 + a] : 0.f;
    }
    __syncthreads();

    // ---- up projections -> packed float4 ----
    {
        const int v = t & 63, mg = t >> 6;
        float a0[8], a1[8][3];
        #pragma unroll
        for (int j = 0; j < 8; j++) { a0[j] = 0.f; a1[j][0] = a1[j][1] = a1[j][2] = 0.f; }
        for (int u = 0; u < 64; u++) {
            float w0 = Wup0[u * 64 + v];
            float w1 = Wup1[u * 64 + v];
            #pragma unroll
            for (int j = 0; j < 8; j++) {
                int m = mg * 8 + j;
                a0[j] += sx0[m * 65 + u] * w0;
                const float* xv = &sx1[m * 193 + u * 3];
                a1[j][0] += xv[0] * w1;
                a1[j][1] += xv[1] * w1;
                a1[j][2] += xv[2] * w1;
            }
        }
        #pragma unroll
        for (int j = 0; j < 8; j++) {
            int n = n0 + mg * 8 + j;
            if (n < NN)
                g_xu[n * 64 + v] = make_float4(a0[j] * 0.125f, a1[j][0] * 0.125f,
                                               a1[j][1] * 0.125f, a1[j][2] * 0.125f);
        }
    }

    // ---- sc_s: P[32x640] @ Wsks[640x128], k-tiled by 80, both operands smem ----
    {
        const int gv = t & 31, gm = t >> 5;
        float acc[4][4];
        #pragma unroll
        for (int j = 0; j < 4; j++) { acc[j][0] = acc[j][1] = acc[j][2] = acc[j][3] = 0.f; }
        for (int kt = 0; kt < 8; kt++) {
            const int k0 = kt * 80;
            __syncthreads();
            // stage W tile (80x128)
            const float4* wsrc = reinterpret_cast<const float4*>(Wsks) + k0 * 32;
            for (int i4 = t; i4 < 80 * 32; i4 += 256)
                reinterpret_cast<float4*>(Wt)[i4] = wsrc[i4];
            // build P tile (32x80, pitch 84)
            for (int idx = t; idx < 32 * 80; idx += 256) {
                int m = idx / 80, kk = idx - m * 80;
                int k = k0 + kk;
                int u = k / 10, a = k - u * 10;
                Pt[m * 84 + kk] = sx0[m * 65 + u] * sat[m * 11 + a];
            }
            __syncthreads();
            #pragma unroll 4
            for (int kk = 0; kk < 80; kk += 4) {
                float4 pj[4];
                #pragma unroll
                for (int j = 0; j < 4; j++)
                    pj[j] = *reinterpret_cast<const float4*>(&Pt[(gm * 4 + j) * 84 + kk]);
                #pragma unroll
                for (int k2 = 0; k2 < 4; k2++) {
                    float4 b = *reinterpret_cast<const float4*>(&Wt[(kk + k2) * 128 + gv * 4]);
                    #pragma unroll
                    for (int j = 0; j < 4; j++) {
                        float a = (k2 == 0) ? pj[j].x : (k2 == 1) ? pj[j].y : (k2 == 2) ? pj[j].z : pj[j].w;
                        acc[j][0] += a * b.x; acc[j][1] += a * b.y;
                        acc[j][2] += a * b.z; acc[j][3] += a * b.w;
                    }
                }
            }
        }
        #pragma unroll
        for (int j = 0; j < 4; j++) {
            int n = n0 + gm * 4 + j;
            if (n < NN) {
                #pragma unroll
                for (int l = 0; l < 4; l++) g_scs[n * 128 + gv * 4 + l] = acc[j][l] * SKN;
            }
        }
    }

    // ---- sc_v: Pv[96x640] @ Wskv[640x64]; rows = m*3+i ----
    {
        const int gv = t & 15, gm = t >> 4;     // v-group of 4, m-group of 2
        float acc[2][3][4];
        #pragma unroll
        for (int jm = 0; jm < 2; jm++)
            #pragma unroll
            for (int i = 0; i < 3; i++)
                #pragma unroll
                for (int l = 0; l < 4; l++) acc[jm][i][l] = 0.f;
        for (int kt = 0; kt < 8; kt++) {
            const int k0 = kt * 80;
            __syncthreads();
            // stage W tile (80x64)
            const float4* wsrc = reinterpret_cast<const float4*>(Wskv) + k0 * 16;
            for (int i4 = t; i4 < 80 * 16; i4 += 256)
                reinterpret_cast<float4*>(Wt)[i4] = wsrc[i4];
            // build Pv tile (96x80, pitch 84), row = m*3+i
            for (int idx = t; idx < 96 * 80; idx += 256) {
                int row = idx / 80, kk = idx - row * 80;
                int m = row / 3, i = row - m * 3;
                int k = k0 + kk;
                int u = k / 10, a = k - u * 10;
                Pt[row * 84 + kk] = sx1[m * 193 + u * 3 + i] * sat[m * 11 + a];
            }
            __syncthreads();
            #pragma unroll 2
            for (int kk = 0; kk < 80; kk += 4) {
                float4 pv[2][3];
                #pragma unroll
                for (int jm = 0; jm < 2; jm++)
                    #pragma unroll
                    for (int i = 0; i < 3; i++)
                        pv[jm][i] = *reinterpret_cast<const float4*>(
                            &Pt[((gm * 2 + jm) * 3 + i) * 84 + kk]);
                #pragma unroll
                for (int k2 = 0; k2 < 4; k2++) {
                    float4 b = *reinterpret_cast<const float4*>(&Wt[(kk + k2) * 64 + gv * 4]);
                    #pragma unroll
                    for (int jm = 0; jm < 2; jm++)
                        #pragma unroll
                        for (int i = 0; i < 3; i++) {
                            float a = (k2 == 0) ? pv[jm][i].x : (k2 == 1) ? pv[jm][i].y
                                    : (k2 == 2) ? pv[jm][i].z : pv[jm][i].w;
                            acc[jm][i][0] += a * b.x; acc[jm][i][1] += a * b.y;
                            acc[jm][i][2] += a * b.z; acc[jm][i][3] += a * b.w;
                        }
                }
            }
        }
        #pragma unroll
        for (int jm = 0; jm < 2; jm++) {
            int n = n0 + gm * 2 + jm;
            if (n < NN) {
                #pragma unroll
                for (int l = 0; l < 4; l++)
                    #pragma unroll
                    for (int i = 0; i < 3; i++)
                        g_scv[n * 192 + (gv * 4 + l) * 3 + i] = acc[jm][i][l] * SKN;
            }
        }
    }
}

// ================= CSR build =================
__global__ void hist_k(const int* __restrict__ ei) {
    int e = blockIdx.x * blockDim.x + threadIdx.x;
    if (e < NE) atomicAdd(&g_cnt[ei[NE + e]], 1);
}
__global__ void __launch_bounds__(1024) scan_k() {
    __shared__ int wsum[32];
    const int t = threadIdx.x;
    const int lane = t & 31, w = t >> 5;
    int base = t * 10, loc[10], s = 0;
    #pragma unroll
    for (int i = 0; i < 10; i++) {
        int idx = base + i;
        loc[i] = (idx < NN) ? g_cnt[idx] : 0;
        if (idx < NN) g_cnt[idx] = 0;
        s += loc[i];
    }
    int v = s;
    #pragma unroll
    for (int off = 1; off < 32; off <<= 1) {
        int n = __shfl_up_sync(0xFFFFFFFFu, v, off);
        if (lane >= off) v += n;
    }
    if (lane == 31) wsum[w] = v;
    __syncthreads();
    if (w == 0) {
        int x = wsum[lane];
        #pragma unroll
        for (int off = 1; off < 32; off <<= 1) {
            int n = __shfl_up_sync(0xFFFFFFFFu, x, off);
            if (lane >= off) x += n;
        }
        wsum[lane] = x;
    }
    __syncthreads();
    int run = v - s + ((w > 0) ? wsum[w - 1] : 0);
    #pragma unroll
    for (int i = 0; i < 10; i++) {
        int idx = base + i;
        if (idx < NN) { g_row[idx] = run; g_cur[idx] = run; run += loc[i]; }
    }
    if (t == 1023) g_row[NN] = run;
}
__global__ void fill_k(const int* __restrict__ ei) {
    int e = blockIdx.x * blockDim.x + threadIdx.x;
    if (e < NE) {
        int pos = atomicAdd(&g_cur[ei[NE + e]], 1);
        g_csr[pos] = e;
    }
}
__global__ void sort_k(const int* __restrict__ ei) {
    int n = blockIdx.x * blockDim.x + threadIdx.x;
    if (n < NN) {
        int b = g_row[n], e = g_row[n + 1];
        for (int i = b + 1; i < e; i++) {
            int v = g_csr[i], j = i - 1;
            while (j >= b && g_csr[j] > v) { g_csr[j + 1] = g_csr[j]; j--; }
            g_csr[j + 1] = v;
        }
        for (int i = b; i < e; i++) g_snd[i] = ei[g_csr[i]];
    }
}

// ================= K2: fused edge MLP (scalar FFMA) =================
__device__ __forceinline__ void layer64(const float* __restrict__ hin,
                                        const float* __restrict__ W,
                                        float* __restrict__ hout, int t)
{
    const int gv = t & 15, ge = t >> 4;
    float acc[4][4];
    #pragma unroll
    for (int j = 0; j < 4; j++) { acc[j][0] = acc[j][1] = acc[j][2] = acc[j][3] = 0.f; }
    #pragma unroll 4
    for (int k0 = 0; k0 < 64; k0 += 4) {
        float4 aj[4];
        #pragma unroll
        for (int j = 0; j < 4; j++)
            aj[j] = *reinterpret_cast<const float4*>(&hin[(ge * 4 + j) * 68 + k0]);
        #pragma unroll
        for (int kk = 0; kk < 4; kk++) {
            float4 b = *reinterpret_cast<const float4*>(&W[(k0 + kk) * 64 + gv * 4]);
            #pragma unroll
            for (int j = 0; j < 4; j++) {
                float a = (kk == 0) ? aj[j].x : (kk == 1) ? aj[j].y : (kk == 2) ? aj[j].z : aj[j].w;
                acc[j][0] += a * b.x; acc[j][1] += a * b.y;
                acc[j][2] += a * b.z; acc[j][3] += a * b.w;
            }
        }
    }
    #pragma unroll
    for (int j = 0; j < 4; j++)
        #pragma unroll
        for (int l = 0; l < 4; l++)
            hout[(ge * 4 + j) * 68 + gv * 4 + l] = silu_f(acc[j][l] * 0.125f);
}

__global__ void __launch_bounds__(256) edge_mlp(
    const float* __restrict__ ef, const float* __restrict__ M1,
    const float* __restrict__ M2, const float* __restrict__ M3,
    const float* __restrict__ M4)
{
    __shared__ float ef_s[64 * 9];
    __shared__ float ha[64 * 68];
    __shared__ float hb[64 * 68];
    const int t = threadIdx.x;
    const int e0 = blockIdx.x * 64;

    for (int idx = t; idx < 64 * 8; idx += 256) {
        int m = idx >> 3, k = idx & 7;
        ef_s[m * 9 + k] = ef[(size_t)(e0 + m) * 8 + k];
    }
    __syncthreads();

    {
        const int gv = t & 15, ge = t >> 4;
        float acc[4][4];
        #pragma unroll
        for (int j = 0; j < 4; j++) { acc[j][0] = acc[j][1] = acc[j][2] = acc[j][3] = 0.f; }
        #pragma unroll
        for (int k = 0; k < 8; k++) {
            float4 b = *reinterpret_cast<const float4*>(&M1[k * 64 + gv * 4]);
            #pragma unroll
            for (int j = 0; j < 4; j++) {
                float a = ef_s[(ge * 4 + j) * 9 + k];
                acc[j][0] += a * b.x; acc[j][1] += a * b.y;
                acc[j][2] += a * b.z; acc[j][3] += a * b.w;
            }
        }
        #pragma unroll
        for (int j = 0; j < 4; j++)
            #pragma unroll
            for (int l = 0; l < 4; l++)
                ha[(ge * 4 + j) * 68 + gv * 4 + l] = silu_f(acc[j][l] * 0.35355339059327373f);
    }
    __syncthreads();
    layer64(ha, M2, hb, t);
    __syncthreads();
    layer64(hb, M3, ha, t);
    __syncthreads();

    {
        const int ce = t & 63, eg = t >> 6;
        #pragma unroll
        for (int rep = 0; rep < 4; rep++) {
            int eb = (rep * 4 + eg) * 4;
            float acc[4][4];
            #pragma unroll
            for (int j = 0; j < 4; j++) { acc[j][0] = acc[j][1] = acc[j][2] = acc[j][3] = 0.f; }
            #pragma unroll 4
            for (int k0 = 0; k0 < 64; k0 += 4) {
                float4 aj[4];
                #pragma unroll
                for (int j = 0; j < 4; j++)
                    aj[j] = *reinterpret_cast<const float4*>(&ha[(eb + j) * 68 + k0]);
                #pragma unroll
                for (int kk = 0; kk < 4; kk++) {
                    float4 b = *reinterpret_cast<const float4*>(&M4[(k0 + kk) * 256 + ce * 4]);
                    #pragma unroll
                    for (int j = 0; j < 4; j++) {
                        float a = (kk == 0) ? aj[j].x : (kk == 1) ? aj[j].y : (kk == 2) ? aj[j].z : aj[j].w;
                        acc[j][0] += a * b.x; acc[j][1] += a * b.y;
                        acc[j][2] += a * b.z; acc[j][3] += a * b.w;
                    }
                }
            }
            #pragma unroll
            for (int j = 0; j < 4; j++) {
                float4 o = make_float4(acc[j][0] * 0.125f, acc[j][1] * 0.125f,
                                       acc[j][2] * 0.125f, acc[j][3] * 0.125f);
                *reinterpret_cast<float4*>(&g_tw[(size_t)(e0 + eb + j) * 256 + ce * 4]) = o;
            }
        }
    }
}

// ================= K4: gather (2-way edge split) + linear + gate + output ======
__global__ void __launch_bounds__(256) gather_final(
    const float* __restrict__ ear, const float* __restrict__ eai,
    const float* __restrict__ Wls, const float* __restrict__ Wlv,
    float* __restrict__ out)
{
    __shared__ float2 sms[2][2][128];
    __shared__ float2 smv[2][2][128][3];
    __shared__ float sfin[2][64][10];
    const int t = threadIdx.x;
    const int g = t >> 7, r = (t >> 6) & 1, v = t & 63;
    const int n = blockIdx.x * 2 + g;

    float msr0 = 0.f, msr1 = 0.f, msi0 = 0.f, msi1 = 0.f;
    float mvr0[3] = {0.f, 0.f, 0.f}, mvr1[3] = {0.f, 0.f, 0.f};
    float mvi0[3] = {0.f, 0.f, 0.f}, mvi1[3] = {0.f, 0.f, 0.f};

    if (n < NN) {
        int b = g_row[n], ed = g_row[n + 1];
        for (int idx = b + r; idx < ed; idx += 2) {
            int e = g_csr[idx];
            int s = g_snd[idx];
            float4 yr = *reinterpret_cast<const float4*>(&ear[e * 4]);
            float4 yi = *reinterpret_cast<const float4*>(&eai[e * 4]);
            float4 x = g_xu[s * 64 + v];
            const float* twp = &g_tw[(size_t)e * 256];
            float wA = twp[v], wB = twp[64 + v], wC = twp[128 + v], wD = twp[192 + v];

            float dr = x.y * yr.y + x.z * yr.z + x.w * yr.w;
            float di = x.y * yi.y + x.z * yi.z + x.w * yi.w;
            msr0 += x.x * yr.x * wA;
            msi0 += x.x * yi.x * wA;
            msr1 += dr * INV3 * wD;
            msi1 += di * INV3 * wD;
            float xb = x.x * wB;
            mvr0[0] += xb * yr.y; mvr0[1] += xb * yr.z; mvr0[2] += xb * yr.w;
            mvi0[0] += xb * yi.y; mvi0[1] += xb * yi.z; mvi0[2] += xb * yi.w;
            float tcr = yr.x * wC, tci = yi.x * wC;
            mvr1[0] += x.y * tcr; mvr1[1] += x.z * tcr; mvr1[2] += x.w * tcr;
            mvi1[0] += x.y * tci; mvi1[1] += x.z * tci; mvi1[2] += x.w * tci;
        }
    }
    sms[g][r][v] = make_float2(msr0, msi0);
    sms[g][r][64 + v] = make_float2(msr1, msi1);
    #pragma unroll
    for (int i = 0; i < 3; i++) {
        smv[g][r][v][i] = make_float2(mvr0[i], mvi0[i]);
        smv[g][r][64 + v][i] = make_float2(mvr1[i], mvi1[i]);
    }
    __syncthreads();

    {
        int u = r * 64 + v;
        float2 a = sms[g][0][u], b = sms[g][1][u];
        sms[g][0][u] = make_float2(a.x + b.x, a.y + b.y);
        #pragma unroll
        for (int i = 0; i < 3; i++) {
            float2 c = smv[g][0][u][i], d = smv[g][1][u][i];
            smv[g][0][u][i] = make_float2(c.x + d.x, c.y + d.y);
        }
    }
    __syncthreads();

    float lsr0 = 0.f, lsr1 = 0.f, lsi0 = 0.f, lsi1 = 0.f;
    float lvr[3] = {0.f, 0.f, 0.f}, lvi[3] = {0.f, 0.f, 0.f};
    const int ub = r * 64;
    #pragma unroll 4
    for (int u2 = 0; u2 < 64; u2++) {
        int u = ub + u2;
        float wa = Wls[u * 128 + v];
        float wb = Wls[u * 128 + 64 + v];
        float wv = Wlv[u * 64 + v];
        float2 m = sms[g][0][u];
        lsr0 += m.x * wa; lsr1 += m.x * wb;
        lsi0 += m.y * wa; lsi1 += m.y * wb;
        #pragma unroll
        for (int i = 0; i < 3; i++) {
            float2 mv = smv[g][0][u][i];
            lvr[i] += mv.x * wv;
            lvi[i] += mv.y * wv;
        }
    }

    if (r == 1) {
        float* p = sfin[g][v];
        p[0] = lsr0; p[1] = lsr1; p[2] = lsi0; p[3] = lsi1;
        p[4] = lvr[0]; p[5] = lvr[1]; p[6] = lvr[2];
        p[7] = lvi[0]; p[8] = lvi[1]; p[9] = lvi[2];
    }
    __syncthreads();
    if (r == 0 && n < NN) {
        const float* p = sfin[g][v];
        lsr0 += p[0]; lsr1 += p[1]; lsi0 += p[2]; lsi1 += p[3];
        lvr[0] += p[4]; lvr[1] += p[5]; lvr[2] += p[6];
        lvi[0] += p[7]; lvi[1] += p[8]; lvi[2] += p[9];

        float sr0 = lsr0 * LN + g_scs[n * 128 + v];
        float sr1 = lsr1 * LN + g_scs[n * 128 + 64 + v];
        float scal_r = silu_f(sr0);
        float gr = silu_f(sr1);
        float scal_i = silu_f(lsi0 * LN);
        float gi = silu_f(lsi1 * LN);
        float* o = out + (size_t)n * 512;
        o[v * 2 + 0] = scal_r;
        o[v * 2 + 1] = scal_i;
        #pragma unroll
        for (int i = 0; i < 3; i++) {
            float vr = (lvr[i] * LN + g_scv[n * 192 + v * 3 + i]) * gr;
            float vi = (lvi[i] * LN) * gi;
            int k = 64 + v * 3 + i;
            o[k * 2 + 0] = vr;
            o[k * 2 + 1] = vi;
        }
    }
}

// ================= launch =================
extern "C" void kernel_launch(void* const* d_in, const int* in_sizes, int n_in,
                              void* d_out, int out_size)
{
    const float* node_attrs = (const float*)d_in[0];
    const float* node_feats = (const float*)d_in[1];
    const float* ear        = (const float*)d_in[2];
    const float* eai        = (const float*)d_in[3];
    const float* ef         = (const float*)d_in[4];
    const float* Wup0       = (const float*)d_in[5];
    const float* Wup1       = (const float*)d_in[6];
    const float* M1         = (const float*)d_in[7];
    const float* M2         = (const float*)d_in[8];
    const float* M3         = (const float*)d_in[9];
    const float* M4         = (const float*)d_in[10];
    const float* Wls        = (const float*)d_in[11];
    const float* Wlv        = (const float*)d_in[12];
    const float* Wsks       = (const float*)d_in[13];
    const float* Wskv       = (const float*)d_in[14];
    const int*   ei         = (const int*)d_in[15];
    float* out = (float*)d_out;

    const int np_smem = NP_SMEM_FLOATS * 4;  // 107648 B
    cudaFuncSetAttribute(node_prep, cudaFuncAttributeMaxDynamicSharedMemorySize, np_smem);

    // node_prep stays at launch index 3 (the slot ncu captures)
    hist_k<<<(NE + 255) / 256, 256>>>(ei);
    scan_k<<<1, 1024>>>();
    fill_k<<<(NE + 255) / 256, 256>>>(ei);
    node_prep<<<(NN + 31) / 32, 256, np_smem>>>(node_attrs, node_feats, Wup0, Wup1, Wsks, Wskv);
    sort_k<<<(NN + 127) / 128, 128>>>(ei);
    edge_mlp<<<NE / 64, 256>>>(ef, M1, M2, M3, M4);
    gather_final<<<(NN + 1) / 2, 256>>>(ear, eai, Wls, Wlv, out);
}